// round 8
// baseline (speedup 1.0000x reference)
#include <cuda_runtime.h>
#include <cstdint>

#define IMG_H 512
#define IMG_W 512
#define TILE_H 16
#define NTHREADS 256   // thread owns cols 2t, 2t+1

__device__ __forceinline__ int reflr(int g) {
    // reflect-101: -1 -> 1, -2 -> 2, 512 -> 510, 513 -> 509
    g = g < 0 ? -g : g;
    if (g >= IMG_H) g = 2 * IMG_H - 2 - g;
    return g;
}

__device__ __forceinline__ float2 ld2(const float* p) {
    return *reinterpret_cast<const float2*>(p);
}

// ---- packed f32x2 helpers (sm_103a) ----
__device__ __forceinline__ uint64_t pack2(float x, float y) {
    uint64_t r; asm("mov.b64 %0, {%1, %2};" : "=l"(r) : "f"(x), "f"(y)); return r;
}
__device__ __forceinline__ uint64_t addx2(uint64_t a, uint64_t b) {
    uint64_t r; asm("add.rn.f32x2 %0, %1, %2;" : "=l"(r) : "l"(a), "l"(b)); return r;
}
__device__ __forceinline__ uint64_t mulx2(uint64_t a, uint64_t b) {
    uint64_t r; asm("mul.rn.f32x2 %0, %1, %2;" : "=l"(r) : "l"(a), "l"(b)); return r;
}
// a*b + c  (used as subtract with b = packed(-1,-1))
__device__ __forceinline__ uint64_t fmax2(uint64_t a, uint64_t b, uint64_t c) {
    uint64_t r; asm("fma.rn.f32x2 %0, %1, %2, %3;" : "=l"(r) : "l"(a), "l"(b), "l"(c)); return r;
}

struct Row { float2 A, B, C; };

__device__ __forceinline__ Row ldrow(const float* __restrict__ rp, int c0,
                                     bool isL, bool isR)
{
    Row r;
    r.A = isL ? make_float2(0.f, 0.f) : ld2(rp + c0 - 2);
    r.B = ld2(rp + c0);
    r.C = isR ? make_float2(0.f, 0.f) : ld2(rp + c0 + 2);
    return r;
}

// Horizontal 5-tap sums (packed result) from A=(c-2,c-1), B=(c,c+1), C=(c+2,c+3).
// Edge lanes patch by register rename (reflect-101):
//   t=0:   A=(C.x,B.y)   [cols -2,-1 -> 2,1]
//   t=255: C=(B.x,A.y)   [cols 512,513 -> 510,509]
__device__ __forceinline__ uint64_t hsum2p(Row r, bool isL, bool isR)
{
    float2 A = r.A, B = r.B, C = r.C;
    if (isL) { A.x = C.x; A.y = B.y; }
    if (isR) { C.x = B.x; C.y = A.y; }
    float u = A.y + B.x + B.y + C.x;
    return pack2(u + A.x, u + C.y);
}

__global__ __launch_bounds__(NTHREADS, 6)
void smooth5_kernel(const float* __restrict__ in, float* __restrict__ out)
{
    const int tid   = threadIdx.x;
    const int c0    = 2 * tid;
    const int plane = blockIdx.y;
    const int row0  = blockIdx.x * TILE_H;

    const float* ip = in  + (size_t)plane * (IMG_H * IMG_W);
    float*       op = out + (size_t)plane * (IMG_H * IMG_W);

    const bool isL = (tid == 0);
    const bool isR = (tid == NTHREADS - 1);

    const uint64_t inv25x2 = pack2(1.0f / 25.0f, 1.0f / 25.0f);
    const uint64_t negone  = pack2(-1.0f, -1.0f);

    // Warm-up: H of source rows row0-2 .. row0+1 (reflected at top edge)
    uint64_t q0 = hsum2p(ldrow(ip + (size_t)reflr(row0 - 2) * IMG_W, c0, isL, isR), isL, isR);
    uint64_t q1 = hsum2p(ldrow(ip + (size_t)reflr(row0 - 1) * IMG_W, c0, isL, isR), isL, isR);
    uint64_t q2 = hsum2p(ldrow(ip + (size_t)(row0)          * IMG_W, c0, isL, isR), isL, isR);
    uint64_t q3 = hsum2p(ldrow(ip + (size_t)(row0 + 1)      * IMG_W, c0, isL, isR), isL, isR);
    uint64_t S  = addx2(addx2(q0, q1), addx2(q2, q3));   // H(r-2..r+1)

    if (row0 + TILE_H + 2 <= IMG_H) {
        // ---------- interior fast path: depth-2 load pipeline ----------
        const float* sp = ip + (size_t)(row0 + 2) * IMG_W;
        float*       dp = op + (size_t)(row0)     * IMG_W + c0;

        Row p0 = ldrow(sp, c0, isL, isR); sp += IMG_W;   // source row row0+2
        Row p1 = ldrow(sp, c0, isL, isR); sp += IMG_W;   // source row row0+3

        #pragma unroll
        for (int r = 0; r < TILE_H; ++r) {
            Row cur = p0;
            p0 = p1;
            if (r < TILE_H - 2) {                        // prefetch row r+4
                p1 = ldrow(sp, c0, isL, isR);
                sp += IMG_W;
            }
            uint64_t h = hsum2p(cur, isL, isR);          // H(r+2)
            S = addx2(S, h);                             // 5-term window
            uint64_t o = mulx2(S, inv25x2);
            __stcs(reinterpret_cast<float2*>(dp), *reinterpret_cast<float2*>(&o));
            dp += IMG_W;
            S = fmax2(q0, negone, S);                    // drop H(r-2)
            q0 = q1; q1 = q2; q2 = q3; q3 = h;
        }
    } else {
        // ---------- bottom tile: reflected row indexing ----------
        #pragma unroll
        for (int r = 0; r < TILE_H; ++r) {
            const float* rp = ip + (size_t)reflr(row0 + 2 + r) * IMG_W;
            uint64_t h = hsum2p(ldrow(rp, c0, isL, isR), isL, isR);
            S = addx2(S, h);
            uint64_t o = mulx2(S, inv25x2);
            __stcs(reinterpret_cast<float2*>(op + (size_t)(row0 + r) * IMG_W + c0),
                   *reinterpret_cast<float2*>(&o));
            S = fmax2(q0, negone, S);
            q0 = q1; q1 = q2; q2 = q3; q3 = h;
        }
    }
}

extern "C" void kernel_launch(void* const* d_in, const int* in_sizes, int n_in,
                              void* d_out, int out_size)
{
    const float* in  = (const float*)d_in[0];
    float*       out = (float*)d_out;
    int planes = in_sizes[0] / (IMG_H * IMG_W);   // B*C = 96
    dim3 grid(IMG_H / TILE_H, planes);
    smooth5_kernel<<<grid, NTHREADS>>>(in, out);
}